// round 10
// baseline (speedup 1.0000x reference)
#include <cuda_runtime.h>
#include <cuda_bf16.h>

// Problem constants (fixed by setup_inputs)
#define CH    16
#define HH    512
#define WW    512
#define KS    7
#define RAD   3
#define DIL   2
#define PAD   6            // RAD*DIL
#define DYN   3            // output channels

// Tiling: 32 x 24 pixels per block, 256 threads, 3 pixels per thread
#define TW    32
#define TPH   24
#define LW    (TW + 2*PAD)   // 44
#define LH    (TPH + 2*PAD)  // 36
#define PLANE (LW*LH)        // 1584
#define NTHREADS 256
#define NPAIR 8              // channel pairs
#define NQUAD 4              // channel quads

#define SMEM_BYTES (17 * PLANE * 4)   // 16 channel planes + s2 plane = 107712 B

#define LOG2E 1.4426950408889634f

typedef unsigned long long u64;

__device__ __forceinline__ u64 pk2(float lo, float hi) {
    u64 r; asm("mov.b64 %0,{%1,%2};" : "=l"(r) : "f"(lo), "f"(hi)); return r;
}
__device__ __forceinline__ void upk2(u64 v, float& lo, float& hi) {
    asm("mov.b64 {%0,%1},%2;" : "=f"(lo), "=f"(hi) : "l"(v));
}
__device__ __forceinline__ u64 ffma2(u64 a, u64 b, u64 c) {
    u64 d; asm("fma.rn.f32x2 %0,%1,%2,%3;" : "=l"(d) : "l"(a), "l"(b), "l"(c)); return d;
}
__device__ __forceinline__ u64 fadd2(u64 a, u64 b) {
    u64 d; asm("add.rn.f32x2 %0,%1,%2;" : "=l"(d) : "l"(a), "l"(b)); return d;
}
__device__ __forceinline__ u64 fmul2(u64 a, u64 b) {
    u64 d; asm("mul.rn.f32x2 %0,%1,%2;" : "=l"(d) : "l"(a), "l"(b)); return d;
}
__device__ __forceinline__ float ex2(float x) {
    float r; asm("ex2.approx.f32 %0,%1;" : "=f"(r) : "f"(x)); return r;
}

__global__ __launch_bounds__(NTHREADS, 2)
void bilateral_kernel(const float* __restrict__ in,
                      const float* __restrict__ prm,
                      float* __restrict__ out)
{
    extern __shared__ float smf[];
    // Quad-interleaved tile: ulonglong2 view [NQUAD][PLANE]; quad q holds ch 4q..4q+3
    ulonglong2* Tq  = (ulonglong2*)smf;
    float*      s2t = smf + CH * PLANE;     // [LH][LW], -1e30 marks OOB pixels

    const int tx  = threadIdx.x;         // 0..31
    const int ty  = threadIdx.y;         // 0..7
    const int tid = ty * TW + tx;
    const int bx0 = blockIdx.x * TW;
    const int by0 = blockIdx.y * TPH;
    const int b   = blockIdx.z;

    // Coefficients pre-scaled by log2(e) -> raw ex2
    float rcl[CH];
    #pragma unroll
    for (int c = 0; c < CH; c++) rcl[c] = __ldg(&prm[c]) * LOG2E;
    const float sxl = __ldg(&prm[CH]) * LOG2E;
    const float syl = __ldg(&prm[CH + 1]) * LOG2E;

    const float* inb = in + (size_t)b * CH * HH * WW;

    // ---- Phase 1: load haloed tile into quad-interleaved smem (zero-fill OOB) ----
    // Linear float index idx -> quad q = idx/(4*PLANE), p = (idx%(4*PLANE))>>2,
    // channel = 4q + (idx&3). Writes are sequential -> conflict-free STS.
    for (int idx = tid; idx < CH * PLANE; idx += NTHREADS) {
        int q    = idx / (4 * PLANE);
        int rem  = idx - q * (4 * PLANE);
        int p    = rem >> 2;
        int c    = 4 * q + (rem & 3);
        int lr = p / LW;
        int lc = p - lr * LW;
        int gy = by0 + lr - PAD;
        int gx = bx0 + lc - PAD;
        float v = 0.0f;
        if ((unsigned)gy < (unsigned)HH && (unsigned)gx < (unsigned)WW)
            v = __ldg(&inb[(size_t)c * HH * WW + (size_t)gy * WW + gx]);
        smf[idx] = v;
    }
    __syncthreads();

    // ---- Phase 2: s2'(q) = log2e * sum_c rc_c * x_c(q)^2 ; -1e30 where OOB ----
    for (int p = tid; p < PLANE; p += NTHREADS) {
        int lr = p / LW;
        int lc = p - lr * LW;
        int gy = by0 + lr - PAD;
        int gx = bx0 + lc - PAD;
        float s = -1e30f;
        if ((unsigned)gy < (unsigned)HH && (unsigned)gx < (unsigned)WW) {
            float a0 = 0.f, a1 = 0.f, a2 = 0.f, a3 = 0.f;
            #pragma unroll
            for (int q = 0; q < NQUAD; q++) {
                ulonglong2 v = Tq[q * PLANE + p];
                float x0, x1, x2, x3;
                upk2(v.x, x0, x1);
                upk2(v.y, x2, x3);
                a0 = fmaf(rcl[4*q + 0] * x0, x0, a0);
                a1 = fmaf(rcl[4*q + 1] * x1, x1, a1);
                a2 = fmaf(rcl[4*q + 2] * x2, x2, a2);
                a3 = fmaf(rcl[4*q + 3] * x3, x3, a3);
            }
            s = (a0 + a1) + (a2 + a3);
        }
        s2t[p] = s;
    }
    __syncthreads();

    // ---- Phase 3: three pixels per thread (rows lr0, lr0+2, lr0+4 share tap rows) ----
    // ty 0..7 -> lr0 = 6*(ty>>1) + (ty&1): triples {0,2,4},{1,3,5},{6,8,10},{7,9,11},...
    const int lr0 = 6 * (ty >> 1) + (ty & 1);
    const int cp0 = (lr0 + PAD) * LW + (tx + PAD);
    const int cp1 = cp0 + 2 * LW;
    const int cp2 = cp0 + 4 * LW;

    u64 rcn2[NPAIR];
    #pragma unroll
    for (int k = 0; k < NPAIR; k++)
        rcn2[k] = pk2(-2.0f * rcl[2*k], -2.0f * rcl[2*k + 1]);

    u64 y0p[NPAIR], y1p[NPAIR], y2p[NPAIR];
    #pragma unroll
    for (int q = 0; q < NQUAD; q++) {
        ulonglong2 v0 = Tq[q * PLANE + cp0];
        ulonglong2 v1 = Tq[q * PLANE + cp1];
        ulonglong2 v2 = Tq[q * PLANE + cp2];
        y0p[2*q]   = fmul2(rcn2[2*q],   v0.x);
        y0p[2*q+1] = fmul2(rcn2[2*q+1], v0.y);
        y1p[2*q]   = fmul2(rcn2[2*q],   v1.x);
        y1p[2*q+1] = fmul2(rcn2[2*q+1], v1.y);
        y2p[2*q]   = fmul2(rcn2[2*q],   v2.x);
        y2p[2*q+1] = fmul2(rcn2[2*q+1], v2.y);
    }
    const float s2p0 = s2t[cp0];
    const float s2p1 = s2t[cp1];
    const float s2p2 = s2t[cp2];

    float sxj[KS];
    #pragma unroll
    for (int j = 0; j < KS; j++) {
        float dxf = (float)((j - RAD) * DIL);
        sxj[j] = sxl * dxf * dxf;
    }

    float n00 = 0.f, n01 = 0.f, n02 = 0.f, d0 = 0.f;
    float n10 = 0.f, n11 = 0.f, n12 = 0.f, d1 = 0.f;
    float n20 = 0.f, n21 = 0.f, n22 = 0.f, d2 = 0.f;

    // Tap rows (padded coords): lr0 + 2*i, i = 0..8.
    // px0 valid i in [0,6] (dy0=2i-6); px1 valid [1,7] (dy1=2i-8); px2 valid [2,8] (dy2=2i-10).
    #pragma unroll 1
    for (int i = 0; i < 9; i++) {
        const float dy0 = (float)(2 * i - 6);
        const float dy1 = (float)(2 * i - 8);
        const float dy2 = (float)(2 * i - 10);
        float base0 = fmaf(syl * dy0, dy0, s2p0);
        float base1 = fmaf(syl * dy1, dy1, s2p1);
        float base2 = fmaf(syl * dy2, dy2, s2p2);
        if (i >= 7) base0 = -3e30f;              // rows invalid for px0 -> w=0
        if (i == 0 || i == 8) base1 = -3e30f;    // invalid for px1
        if (i <= 1) base2 = -3e30f;              // invalid for px2
        const int rowoff = (lr0 + 2 * i) * LW + tx;

        #pragma unroll
        for (int j = 0; j < KS; j++) {
            const int p = rowoff + 2 * j;
            const float t = s2t[p] + sxj[j];

            const ulonglong2 va = Tq[0 * PLANE + p];
            const ulonglong2 vb = Tq[1 * PLANE + p];
            const ulonglong2 vc = Tq[2 * PLANE + p];
            const ulonglong2 vd = Tq[3 * PLANE + p];

            // px0
            u64 A0 = fmul2(y0p[0], va.x);
            u64 A1 = fmul2(y0p[1], va.y);
            A0 = ffma2(y0p[2], vb.x, A0);
            A1 = ffma2(y0p[3], vb.y, A1);
            A0 = ffma2(y0p[4], vc.x, A0);
            A1 = ffma2(y0p[5], vc.y, A1);
            A0 = ffma2(y0p[6], vd.x, A0);
            A1 = ffma2(y0p[7], vd.y, A1);
            // px1
            u64 B0 = fmul2(y1p[0], va.x);
            u64 B1 = fmul2(y1p[1], va.y);
            B0 = ffma2(y1p[2], vb.x, B0);
            B1 = ffma2(y1p[3], vb.y, B1);
            B0 = ffma2(y1p[4], vc.x, B0);
            B1 = ffma2(y1p[5], vc.y, B1);
            B0 = ffma2(y1p[6], vd.x, B0);
            B1 = ffma2(y1p[7], vd.y, B1);
            // px2
            u64 C0 = fmul2(y2p[0], va.x);
            u64 C1 = fmul2(y2p[1], va.y);
            C0 = ffma2(y2p[2], vb.x, C0);
            C1 = ffma2(y2p[3], vb.y, C1);
            C0 = ffma2(y2p[4], vc.x, C0);
            C1 = ffma2(y2p[5], vc.y, C1);
            C0 = ffma2(y2p[6], vd.x, C0);
            C1 = ffma2(y2p[7], vd.y, C1);

            u64 SA = fadd2(A0, A1);
            u64 SB = fadd2(B0, B1);
            u64 SC = fadd2(C0, C1);
            float salo, sahi, sblo, sbhi, sclo, schi;
            upk2(SA, salo, sahi);
            upk2(SB, sblo, sbhi);
            upk2(SC, sclo, schi);

            const float w0 = ex2((salo + sahi) + (t + base0));
            const float w1 = ex2((sblo + sbhi) + (t + base1));
            const float w2 = ex2((sclo + schi) + (t + base2));

            float x0, x1, x2, x3dummy;
            upk2(va.x, x0, x1);
            upk2(va.y, x2, x3dummy);

            n00 = fmaf(w0, x0, n00);
            n01 = fmaf(w0, x1, n01);
            n02 = fmaf(w0, x2, n02);
            d0 += w0;
            n10 = fmaf(w1, x0, n10);
            n11 = fmaf(w1, x1, n11);
            n12 = fmaf(w1, x2, n12);
            d1 += w1;
            n20 = fmaf(w2, x0, n20);
            n21 = fmaf(w2, x1, n21);
            n22 = fmaf(w2, x2, n22);
            d2 += w2;
        }
    }

    const float inv0 = __fdividef(1.0f, d0);   // den >= 1 (center tap w=1)
    const float inv1 = __fdividef(1.0f, d1);
    const float inv2 = __fdividef(1.0f, d2);
    const int gy0 = by0 + lr0;
    const int gx  = bx0 + tx;
    const size_t CS = (size_t)HH * WW;
    const size_t ob = (size_t)b * DYN * CS + gx;
    if (gy0 < HH) {
        size_t o = ob + (size_t)gy0 * WW;
        out[o]          = n00 * inv0;
        out[o + CS]     = n01 * inv0;
        out[o + 2 * CS] = n02 * inv0;
    }
    if (gy0 + 2 < HH) {
        size_t o = ob + (size_t)(gy0 + 2) * WW;
        out[o]          = n10 * inv1;
        out[o + CS]     = n11 * inv1;
        out[o + 2 * CS] = n12 * inv1;
    }
    if (gy0 + 4 < HH) {
        size_t o = ob + (size_t)(gy0 + 4) * WW;
        out[o]          = n20 * inv2;
        out[o + CS]     = n21 * inv2;
        out[o + 2 * CS] = n22 * inv2;
    }
}

extern "C" void kernel_launch(void* const* d_in, const int* in_sizes, int n_in,
                              void* d_out, int out_size)
{
    const float* in  = (const float*)d_in[0];
    const float* prm = (const float*)d_in[1];
    float*       out = (float*)d_out;

    const int B = in_sizes[0] / (CH * HH * WW);   // = 4

    cudaFuncSetAttribute(bilateral_kernel,
                         cudaFuncAttributeMaxDynamicSharedMemorySize,
                         (int)SMEM_BYTES);

    dim3 block(TW, 8, 1);                              // 256 threads
    dim3 grid(WW / TW, (HH + TPH - 1) / TPH, B);       // 16 x 22 x 4
    bilateral_kernel<<<grid, block, SMEM_BYTES>>>(in, prm, out);
}

// round 11
// speedup vs baseline: 1.0438x; 1.0438x over previous
#include <cuda_runtime.h>
#include <cuda_bf16.h>

// Problem constants (fixed by setup_inputs)
#define CH    16
#define HH    512
#define WW    512
#define KS    7
#define RAD   3
#define DIL   2
#define PAD   6            // RAD*DIL
#define DYN   3            // output channels

// Tiling: 32 x 24 pixels per block, 256 threads, 3 pixels per thread
#define TW    32
#define TPH   24
#define LW    (TW + 2*PAD)   // 44
#define LH    (TPH + 2*PAD)  // 36
#define PLANE (LW*LH)        // 1584
#define NTHREADS 256
#define NPAIR 8              // channel pairs
#define NQUAD 4              // channel quads

#define SMEM_BYTES (17 * PLANE * 4)   // 16 channel planes + s2 plane = 107712 B

#define LOG2E 1.4426950408889634f

typedef unsigned long long u64;

__device__ __forceinline__ u64 pk2(float lo, float hi) {
    u64 r; asm("mov.b64 %0,{%1,%2};" : "=l"(r) : "f"(lo), "f"(hi)); return r;
}
__device__ __forceinline__ void upk2(u64 v, float& lo, float& hi) {
    asm("mov.b64 {%0,%1},%2;" : "=f"(lo), "=f"(hi) : "l"(v));
}
__device__ __forceinline__ u64 ffma2(u64 a, u64 b, u64 c) {
    u64 d; asm("fma.rn.f32x2 %0,%1,%2,%3;" : "=l"(d) : "l"(a), "l"(b), "l"(c)); return d;
}
__device__ __forceinline__ u64 fadd2(u64 a, u64 b) {
    u64 d; asm("add.rn.f32x2 %0,%1,%2;" : "=l"(d) : "l"(a), "l"(b)); return d;
}
__device__ __forceinline__ u64 fmul2(u64 a, u64 b) {
    u64 d; asm("mul.rn.f32x2 %0,%1,%2;" : "=l"(d) : "l"(a), "l"(b)); return d;
}
__device__ __forceinline__ float ex2(float x) {
    float r; asm("ex2.approx.f32 %0,%1;" : "=f"(r) : "f"(x)); return r;
}

// Process one tap row (padded row = lr0 + 2*IROW) for the subset of the 3
// pixels given by literal flags D0/D1/D2 (dead chains removed at compile time).
#define TAP_ROW(IROW, D0, D1, D2, B0, B1, B2)                                  \
do {                                                                           \
    const int rowoff_ = (lr0 + 2 * (IROW)) * LW + tx;                          \
    _Pragma("unroll")                                                          \
    for (int j = 0; j < KS; j++) {                                             \
        const int p_ = rowoff_ + 2 * j;                                        \
        const float t_ = s2t[p_] + sxj[j];                                     \
        const ulonglong2 va = Tq[0 * PLANE + p_];                              \
        const ulonglong2 vb = Tq[1 * PLANE + p_];                              \
        const ulonglong2 vc = Tq[2 * PLANE + p_];                              \
        const ulonglong2 vd = Tq[3 * PLANE + p_];                              \
        float x0_, x1_, x2_, x3d_;                                             \
        upk2(va.x, x0_, x1_);                                                  \
        upk2(va.y, x2_, x3d_);                                                 \
        if (D0) {                                                              \
            u64 A0 = fmul2(y0p[0], va.x);                                      \
            u64 A1 = fmul2(y0p[1], va.y);                                      \
            A0 = ffma2(y0p[2], vb.x, A0);  A1 = ffma2(y0p[3], vb.y, A1);       \
            A0 = ffma2(y0p[4], vc.x, A0);  A1 = ffma2(y0p[5], vc.y, A1);       \
            A0 = ffma2(y0p[6], vd.x, A0);  A1 = ffma2(y0p[7], vd.y, A1);       \
            u64 SA = fadd2(A0, A1);                                            \
            float sl_, sh_;  upk2(SA, sl_, sh_);                               \
            const float w0_ = ex2((sl_ + sh_) + (t_ + (B0)));                  \
            n00 = fmaf(w0_, x0_, n00);                                         \
            n01 = fmaf(w0_, x1_, n01);                                         \
            n02 = fmaf(w0_, x2_, n02);                                         \
            d0 += w0_;                                                         \
        }                                                                      \
        if (D1) {                                                              \
            u64 B0c = fmul2(y1p[0], va.x);                                     \
            u64 B1c = fmul2(y1p[1], va.y);                                     \
            B0c = ffma2(y1p[2], vb.x, B0c);  B1c = ffma2(y1p[3], vb.y, B1c);   \
            B0c = ffma2(y1p[4], vc.x, B0c);  B1c = ffma2(y1p[5], vc.y, B1c);   \
            B0c = ffma2(y1p[6], vd.x, B0c);  B1c = ffma2(y1p[7], vd.y, B1c);   \
            u64 SB = fadd2(B0c, B1c);                                          \
            float sl_, sh_;  upk2(SB, sl_, sh_);                               \
            const float w1_ = ex2((sl_ + sh_) + (t_ + (B1)));                  \
            n10 = fmaf(w1_, x0_, n10);                                         \
            n11 = fmaf(w1_, x1_, n11);                                         \
            n12 = fmaf(w1_, x2_, n12);                                         \
            d1 += w1_;                                                         \
        }                                                                      \
        if (D2) {                                                              \
            u64 C0 = fmul2(y2p[0], va.x);                                      \
            u64 C1 = fmul2(y2p[1], va.y);                                      \
            C0 = ffma2(y2p[2], vb.x, C0);  C1 = ffma2(y2p[3], vb.y, C1);       \
            C0 = ffma2(y2p[4], vc.x, C0);  C1 = ffma2(y2p[5], vc.y, C1);       \
            C0 = ffma2(y2p[6], vd.x, C0);  C1 = ffma2(y2p[7], vd.y, C1);       \
            u64 SC = fadd2(C0, C1);                                            \
            float sl_, sh_;  upk2(SC, sl_, sh_);                               \
            const float w2_ = ex2((sl_ + sh_) + (t_ + (B2)));                  \
            n20 = fmaf(w2_, x0_, n20);                                         \
            n21 = fmaf(w2_, x1_, n21);                                         \
            n22 = fmaf(w2_, x2_, n22);                                         \
            d2 += w2_;                                                         \
        }                                                                      \
    }                                                                          \
} while (0)

__global__ __launch_bounds__(NTHREADS, 2)
void bilateral_kernel(const float* __restrict__ in,
                      const float* __restrict__ prm,
                      float* __restrict__ out)
{
    extern __shared__ float smf[];
    // Quad-interleaved tile: ulonglong2 view [NQUAD][PLANE]; quad q holds ch 4q..4q+3
    ulonglong2* Tq  = (ulonglong2*)smf;
    float*      s2t = smf + CH * PLANE;     // [LH][LW], -1e30 marks OOB pixels

    const int tx  = threadIdx.x;         // 0..31
    const int ty  = threadIdx.y;         // 0..7
    const int tid = ty * TW + tx;
    const int bx0 = blockIdx.x * TW;
    const int by0 = blockIdx.y * TPH;
    const int b   = blockIdx.z;

    // Coefficients pre-scaled by log2(e) -> raw ex2
    float rcl[CH];
    #pragma unroll
    for (int c = 0; c < CH; c++) rcl[c] = __ldg(&prm[c]) * LOG2E;
    const float sxl = __ldg(&prm[CH]) * LOG2E;
    const float syl = __ldg(&prm[CH + 1]) * LOG2E;

    const float* inb = in + (size_t)b * CH * HH * WW;

    // ---- Phase 1: load haloed tile into quad-interleaved smem (zero-fill OOB) ----
    for (int idx = tid; idx < CH * PLANE; idx += NTHREADS) {
        int q    = idx / (4 * PLANE);
        int rem  = idx - q * (4 * PLANE);
        int p    = rem >> 2;
        int c    = 4 * q + (rem & 3);
        int lr = p / LW;
        int lc = p - lr * LW;
        int gy = by0 + lr - PAD;
        int gx = bx0 + lc - PAD;
        float v = 0.0f;
        if ((unsigned)gy < (unsigned)HH && (unsigned)gx < (unsigned)WW)
            v = __ldg(&inb[(size_t)c * HH * WW + (size_t)gy * WW + gx]);
        smf[idx] = v;
    }
    __syncthreads();

    // ---- Phase 2: s2'(q) = log2e * sum_c rc_c * x_c(q)^2 ; -1e30 where OOB ----
    for (int p = tid; p < PLANE; p += NTHREADS) {
        int lr = p / LW;
        int lc = p - lr * LW;
        int gy = by0 + lr - PAD;
        int gx = bx0 + lc - PAD;
        float s = -1e30f;
        if ((unsigned)gy < (unsigned)HH && (unsigned)gx < (unsigned)WW) {
            float a0 = 0.f, a1 = 0.f, a2 = 0.f, a3 = 0.f;
            #pragma unroll
            for (int q = 0; q < NQUAD; q++) {
                ulonglong2 v = Tq[q * PLANE + p];
                float x0, x1, x2, x3;
                upk2(v.x, x0, x1);
                upk2(v.y, x2, x3);
                a0 = fmaf(rcl[4*q + 0] * x0, x0, a0);
                a1 = fmaf(rcl[4*q + 1] * x1, x1, a1);
                a2 = fmaf(rcl[4*q + 2] * x2, x2, a2);
                a3 = fmaf(rcl[4*q + 3] * x3, x3, a3);
            }
            s = (a0 + a1) + (a2 + a3);
        }
        s2t[p] = s;
    }
    __syncthreads();

    // ---- Phase 3: three pixels per thread (rows lr0, lr0+2, lr0+4 share tap rows) ----
    const int lr0 = 6 * (ty >> 1) + (ty & 1);
    const int cp0 = (lr0 + PAD) * LW + (tx + PAD);
    const int cp1 = cp0 + 2 * LW;
    const int cp2 = cp0 + 4 * LW;

    u64 rcn2[NPAIR];
    #pragma unroll
    for (int k = 0; k < NPAIR; k++)
        rcn2[k] = pk2(-2.0f * rcl[2*k], -2.0f * rcl[2*k + 1]);

    u64 y0p[NPAIR], y1p[NPAIR], y2p[NPAIR];
    #pragma unroll
    for (int q = 0; q < NQUAD; q++) {
        ulonglong2 v0 = Tq[q * PLANE + cp0];
        ulonglong2 v1 = Tq[q * PLANE + cp1];
        ulonglong2 v2 = Tq[q * PLANE + cp2];
        y0p[2*q]   = fmul2(rcn2[2*q],   v0.x);
        y0p[2*q+1] = fmul2(rcn2[2*q+1], v0.y);
        y1p[2*q]   = fmul2(rcn2[2*q],   v1.x);
        y1p[2*q+1] = fmul2(rcn2[2*q+1], v1.y);
        y2p[2*q]   = fmul2(rcn2[2*q],   v2.x);
        y2p[2*q+1] = fmul2(rcn2[2*q+1], v2.y);
    }
    const float s2p0 = s2t[cp0];
    const float s2p1 = s2t[cp1];
    const float s2p2 = s2t[cp2];

    float sxj[KS];
    #pragma unroll
    for (int j = 0; j < KS; j++) {
        float dxf = (float)((j - RAD) * DIL);
        sxj[j] = sxl * dxf * dxf;
    }

    float n00 = 0.f, n01 = 0.f, n02 = 0.f, d0 = 0.f;
    float n10 = 0.f, n11 = 0.f, n12 = 0.f, d1 = 0.f;
    float n20 = 0.f, n21 = 0.f, n22 = 0.f, d2 = 0.f;

    // Row validity: px0 i in [0,6] (dy0=2i-6); px1 [1,7] (dy1=2i-8); px2 [2,8] (dy2=2i-10).
    // Peeled edge rows compute ONLY the valid pixel chains (no masked waste).
    TAP_ROW(0, 1, 0, 0, fmaf(syl * 6.0f, 6.0f, s2p0), 0.0f, 0.0f);
    TAP_ROW(1, 1, 1, 0, fmaf(syl * 4.0f, 4.0f, s2p0),
                        fmaf(syl * 6.0f, 6.0f, s2p1), 0.0f);

    #pragma unroll 1
    for (int i = 2; i <= 6; i++) {
        const float dy0 = (float)(2 * i - 6);
        const float dy1 = (float)(2 * i - 8);
        const float dy2 = (float)(2 * i - 10);
        const float base0 = fmaf(syl * dy0, dy0, s2p0);
        const float base1 = fmaf(syl * dy1, dy1, s2p1);
        const float base2 = fmaf(syl * dy2, dy2, s2p2);
        TAP_ROW(i, 1, 1, 1, base0, base1, base2);
    }

    TAP_ROW(7, 0, 1, 1, 0.0f, fmaf(syl * 6.0f, 6.0f, s2p1),
                              fmaf(syl * 4.0f, 4.0f, s2p2));
    TAP_ROW(8, 0, 0, 1, 0.0f, 0.0f, fmaf(syl * 6.0f, 6.0f, s2p2));

    const float inv0 = __fdividef(1.0f, d0);   // den >= 1 (center tap w=1)
    const float inv1 = __fdividef(1.0f, d1);
    const float inv2 = __fdividef(1.0f, d2);
    const int gy0 = by0 + lr0;
    const int gx  = bx0 + tx;
    const size_t CS = (size_t)HH * WW;
    const size_t ob = (size_t)b * DYN * CS + gx;
    if (gy0 < HH) {
        size_t o = ob + (size_t)gy0 * WW;
        out[o]          = n00 * inv0;
        out[o + CS]     = n01 * inv0;
        out[o + 2 * CS] = n02 * inv0;
    }
    if (gy0 + 2 < HH) {
        size_t o = ob + (size_t)(gy0 + 2) * WW;
        out[o]          = n10 * inv1;
        out[o + CS]     = n11 * inv1;
        out[o + 2 * CS] = n12 * inv1;
    }
    if (gy0 + 4 < HH) {
        size_t o = ob + (size_t)(gy0 + 4) * WW;
        out[o]          = n20 * inv2;
        out[o + CS]     = n21 * inv2;
        out[o + 2 * CS] = n22 * inv2;
    }
}

extern "C" void kernel_launch(void* const* d_in, const int* in_sizes, int n_in,
                              void* d_out, int out_size)
{
    const float* in  = (const float*)d_in[0];
    const float* prm = (const float*)d_in[1];
    float*       out = (float*)d_out;

    const int B = in_sizes[0] / (CH * HH * WW);   // = 4

    cudaFuncSetAttribute(bilateral_kernel,
                         cudaFuncAttributeMaxDynamicSharedMemorySize,
                         (int)SMEM_BYTES);

    dim3 block(TW, 8, 1);                              // 256 threads
    dim3 grid(WW / TW, (HH + TPH - 1) / TPH, B);       // 16 x 22 x 4
    bilateral_kernel<<<grid, block, SMEM_BYTES>>>(in, prm, out);
}

// round 12
// speedup vs baseline: 1.0507x; 1.0066x over previous
#include <cuda_runtime.h>
#include <cuda_bf16.h>

// Problem constants (fixed by setup_inputs)
#define CH    16
#define HH    512
#define WW    512
#define KS    7
#define RAD   3
#define DIL   2
#define PAD   6            // RAD*DIL
#define DYN   3            // output channels

// Tiling: 32 x 20 pixels per block, 320 threads, 2 pixels per thread
#define TW    32
#define TPH   20
#define LW    (TW + 2*PAD)   // 44
#define LH    (TPH + 2*PAD)  // 32
#define PLANE (LW*LH)        // 1408
#define NTHREADS 320
#define NPAIR 8              // channel pairs
#define NQUAD 4              // channel quads

#define SMEM_BYTES (17 * PLANE * 4)   // 16 channel planes + s2 plane = 95744 B

#define LOG2E 1.4426950408889634f

typedef unsigned long long u64;

__device__ __forceinline__ u64 pk2(float lo, float hi) {
    u64 r; asm("mov.b64 %0,{%1,%2};" : "=l"(r) : "f"(lo), "f"(hi)); return r;
}
__device__ __forceinline__ void upk2(u64 v, float& lo, float& hi) {
    asm("mov.b64 {%0,%1},%2;" : "=f"(lo), "=f"(hi) : "l"(v));
}
__device__ __forceinline__ u64 ffma2(u64 a, u64 b, u64 c) {
    u64 d; asm("fma.rn.f32x2 %0,%1,%2,%3;" : "=l"(d) : "l"(a), "l"(b), "l"(c)); return d;
}
__device__ __forceinline__ u64 fadd2(u64 a, u64 b) {
    u64 d; asm("add.rn.f32x2 %0,%1,%2;" : "=l"(d) : "l"(a), "l"(b)); return d;
}
__device__ __forceinline__ u64 fmul2(u64 a, u64 b) {
    u64 d; asm("mul.rn.f32x2 %0,%1,%2;" : "=l"(d) : "l"(a), "l"(b)); return d;
}
__device__ __forceinline__ float ex2(float x) {
    float r; asm("ex2.approx.f32 %0,%1;" : "=f"(r) : "f"(x)); return r;
}

// One tap row (padded row = lr0 + 2*IROW) for the subset of the 2 pixels given
// by literal flags D0/D1 (dead chains removed at compile time).
#define TAP_ROW(IROW, D0, D1, B0, B1)                                          \
do {                                                                           \
    const int rowoff_ = (lr0 + 2 * (IROW)) * LW + tx;                          \
    _Pragma("unroll")                                                          \
    for (int j = 0; j < KS; j++) {                                             \
        const int p_ = rowoff_ + 2 * j;                                        \
        const float t_ = s2t[p_] + sxj[j];                                     \
        const ulonglong2 va = Tq[0 * PLANE + p_];                              \
        const ulonglong2 vb = Tq[1 * PLANE + p_];                              \
        const ulonglong2 vc = Tq[2 * PLANE + p_];                              \
        const ulonglong2 vd = Tq[3 * PLANE + p_];                              \
        float x0_, x1_, x2_, x3d_;                                             \
        upk2(va.x, x0_, x1_);                                                  \
        upk2(va.y, x2_, x3d_);                                                 \
        if (D0) {                                                              \
            u64 A0 = fmul2(y0p[0], va.x);                                      \
            u64 A1 = fmul2(y0p[1], va.y);                                      \
            A0 = ffma2(y0p[2], vb.x, A0);  A1 = ffma2(y0p[3], vb.y, A1);       \
            A0 = ffma2(y0p[4], vc.x, A0);  A1 = ffma2(y0p[5], vc.y, A1);       \
            A0 = ffma2(y0p[6], vd.x, A0);  A1 = ffma2(y0p[7], vd.y, A1);       \
            u64 SA = fadd2(A0, A1);                                            \
            float sl_, sh_;  upk2(SA, sl_, sh_);                               \
            const float w0_ = ex2((sl_ + sh_) + (t_ + (B0)));                  \
            n00 = fmaf(w0_, x0_, n00);                                         \
            n01 = fmaf(w0_, x1_, n01);                                         \
            n02 = fmaf(w0_, x2_, n02);                                         \
            d0 += w0_;                                                         \
        }                                                                      \
        if (D1) {                                                              \
            u64 B0c = fmul2(y1p[0], va.x);                                     \
            u64 B1c = fmul2(y1p[1], va.y);                                     \
            B0c = ffma2(y1p[2], vb.x, B0c);  B1c = ffma2(y1p[3], vb.y, B1c);   \
            B0c = ffma2(y1p[4], vc.x, B0c);  B1c = ffma2(y1p[5], vc.y, B1c);   \
            B0c = ffma2(y1p[6], vd.x, B0c);  B1c = ffma2(y1p[7], vd.y, B1c);   \
            u64 SB = fadd2(B0c, B1c);                                          \
            float sl_, sh_;  upk2(SB, sl_, sh_);                               \
            const float w1_ = ex2((sl_ + sh_) + (t_ + (B1)));                  \
            n10 = fmaf(w1_, x0_, n10);                                         \
            n11 = fmaf(w1_, x1_, n11);                                         \
            n12 = fmaf(w1_, x2_, n12);                                         \
            d1 += w1_;                                                         \
        }                                                                      \
    }                                                                          \
} while (0)

__global__ __launch_bounds__(NTHREADS, 2)
void bilateral_kernel(const float* __restrict__ in,
                      const float* __restrict__ prm,
                      float* __restrict__ out)
{
    extern __shared__ float smf[];
    // Quad-interleaved tile: ulonglong2 view [NQUAD][PLANE]; quad q holds ch 4q..4q+3
    ulonglong2* Tq  = (ulonglong2*)smf;
    float*      s2t = smf + CH * PLANE;     // [LH][LW], -1e30 marks OOB pixels

    const int tx  = threadIdx.x;         // 0..31
    const int ty  = threadIdx.y;         // 0..9
    const int tid = ty * TW + tx;
    const int bx0 = blockIdx.x * TW;
    const int by0 = blockIdx.y * TPH;
    const int b   = blockIdx.z;

    // Coefficients pre-scaled by log2(e) -> raw ex2
    float rcl[CH];
    #pragma unroll
    for (int c = 0; c < CH; c++) rcl[c] = __ldg(&prm[c]) * LOG2E;
    const float sxl = __ldg(&prm[CH]) * LOG2E;
    const float syl = __ldg(&prm[CH + 1]) * LOG2E;

    const float* inb = in + (size_t)b * CH * HH * WW;

    // ---- Phase 1: load haloed tile into quad-interleaved smem (zero-fill OOB) ----
    for (int idx = tid; idx < CH * PLANE; idx += NTHREADS) {
        int q    = idx / (4 * PLANE);
        int rem  = idx - q * (4 * PLANE);
        int p    = rem >> 2;
        int c    = 4 * q + (rem & 3);
        int lr = p / LW;
        int lc = p - lr * LW;
        int gy = by0 + lr - PAD;
        int gx = bx0 + lc - PAD;
        float v = 0.0f;
        if ((unsigned)gy < (unsigned)HH && (unsigned)gx < (unsigned)WW)
            v = __ldg(&inb[(size_t)c * HH * WW + (size_t)gy * WW + gx]);
        smf[idx] = v;
    }
    __syncthreads();

    // ---- Phase 2: s2'(q) = log2e * sum_c rc_c * x_c(q)^2 ; -1e30 where OOB ----
    for (int p = tid; p < PLANE; p += NTHREADS) {
        int lr = p / LW;
        int lc = p - lr * LW;
        int gy = by0 + lr - PAD;
        int gx = bx0 + lc - PAD;
        float s = -1e30f;
        if ((unsigned)gy < (unsigned)HH && (unsigned)gx < (unsigned)WW) {
            float a0 = 0.f, a1 = 0.f, a2 = 0.f, a3 = 0.f;
            #pragma unroll
            for (int q = 0; q < NQUAD; q++) {
                ulonglong2 v = Tq[q * PLANE + p];
                float x0, x1, x2, x3;
                upk2(v.x, x0, x1);
                upk2(v.y, x2, x3);
                a0 = fmaf(rcl[4*q + 0] * x0, x0, a0);
                a1 = fmaf(rcl[4*q + 1] * x1, x1, a1);
                a2 = fmaf(rcl[4*q + 2] * x2, x2, a2);
                a3 = fmaf(rcl[4*q + 3] * x3, x3, a3);
            }
            s = (a0 + a1) + (a2 + a3);
        }
        s2t[p] = s;
    }
    __syncthreads();

    // ---- Phase 3: two pixels per thread (rows lr0, lr0+2 share tap rows) ----
    // ty 0..9 -> lr0 = 4*(ty>>1)+(ty&1) in {0,1,4,5,8,9,12,13,16,17};
    // pairs {lr0, lr0+2} tile rows 0..19.
    const int lr0 = 4 * (ty >> 1) + (ty & 1);
    const int cp0 = (lr0 + PAD) * LW + (tx + PAD);
    const int cp1 = cp0 + 2 * LW;

    u64 rcn2[NPAIR];
    #pragma unroll
    for (int k = 0; k < NPAIR; k++)
        rcn2[k] = pk2(-2.0f * rcl[2*k], -2.0f * rcl[2*k + 1]);

    u64 y0p[NPAIR], y1p[NPAIR];
    #pragma unroll
    for (int q = 0; q < NQUAD; q++) {
        ulonglong2 v0 = Tq[q * PLANE + cp0];
        ulonglong2 v1 = Tq[q * PLANE + cp1];
        y0p[2*q]   = fmul2(rcn2[2*q],   v0.x);
        y0p[2*q+1] = fmul2(rcn2[2*q+1], v0.y);
        y1p[2*q]   = fmul2(rcn2[2*q],   v1.x);
        y1p[2*q+1] = fmul2(rcn2[2*q+1], v1.y);
    }
    const float s2p0 = s2t[cp0];
    const float s2p1 = s2t[cp1];

    float sxj[KS];
    #pragma unroll
    for (int j = 0; j < KS; j++) {
        float dxf = (float)((j - RAD) * DIL);
        sxj[j] = sxl * dxf * dxf;
    }

    float n00 = 0.f, n01 = 0.f, n02 = 0.f, d0 = 0.f;
    float n10 = 0.f, n11 = 0.f, n12 = 0.f, d1 = 0.f;

    // Row validity: px0 i in [0,6] (dy0=2i-6); px1 i in [1,7] (dy1=2i-8).
    // Peeled edge rows compute ONLY the valid pixel chain (no masked waste).
    TAP_ROW(0, 1, 0, fmaf(syl * 6.0f, 6.0f, s2p0), 0.0f);

    #pragma unroll 1
    for (int i = 1; i <= 6; i++) {
        const float dy0 = (float)(2 * i - 6);
        const float dy1 = (float)(2 * i - 8);
        const float base0 = fmaf(syl * dy0, dy0, s2p0);
        const float base1 = fmaf(syl * dy1, dy1, s2p1);
        TAP_ROW(i, 1, 1, base0, base1);
    }

    TAP_ROW(7, 0, 1, 0.0f, fmaf(syl * 6.0f, 6.0f, s2p1));

    const float inv0 = __fdividef(1.0f, d0);   // den >= 1 (center tap w=1)
    const float inv1 = __fdividef(1.0f, d1);
    const int gy0 = by0 + lr0;
    const int gy1 = gy0 + 2;
    const int gx  = bx0 + tx;
    const size_t CS = (size_t)HH * WW;
    const size_t ob = (size_t)b * DYN * CS + gx;
    if (gy0 < HH) {
        size_t o = ob + (size_t)gy0 * WW;
        out[o]          = n00 * inv0;
        out[o + CS]     = n01 * inv0;
        out[o + 2 * CS] = n02 * inv0;
    }
    if (gy1 < HH) {
        size_t o = ob + (size_t)gy1 * WW;
        out[o]          = n10 * inv1;
        out[o + CS]     = n11 * inv1;
        out[o + 2 * CS] = n12 * inv1;
    }
}

extern "C" void kernel_launch(void* const* d_in, const int* in_sizes, int n_in,
                              void* d_out, int out_size)
{
    const float* in  = (const float*)d_in[0];
    const float* prm = (const float*)d_in[1];
    float*       out = (float*)d_out;

    const int B = in_sizes[0] / (CH * HH * WW);   // = 4

    cudaFuncSetAttribute(bilateral_kernel,
                         cudaFuncAttributeMaxDynamicSharedMemorySize,
                         (int)SMEM_BYTES);

    dim3 block(TW, 10, 1);                             // 320 threads
    dim3 grid(WW / TW, (HH + TPH - 1) / TPH, B);       // 16 x 26 x 4
    bilateral_kernel<<<grid, block, SMEM_BYTES>>>(in, prm, out);
}

// round 13
// speedup vs baseline: 1.1220x; 1.0679x over previous
#include <cuda_runtime.h>
#include <cuda_bf16.h>

// Problem constants (fixed by setup_inputs)
#define CH    16
#define HH    512
#define WW    512
#define KS    7
#define RAD   3
#define DIL   2
#define PAD   6            // RAD*DIL
#define DYN   3            // output channels

// Tiling: 32 x 24 pixels per block, 384 threads, 2 pixels per thread
#define TW    32
#define TPH   24
#define LW    (TW + 2*PAD)   // 44
#define LH    (TPH + 2*PAD)  // 36
#define PLANE (LW*LH)        // 1584
#define NTHREADS 384
#define NPAIR 8              // channel pairs
#define NQUAD 4              // channel quads

#define SMEM_BYTES (17 * PLANE * 4)   // 16 channel planes + s2 plane = 107712 B

#define LOG2E 1.4426950408889634f

typedef unsigned long long u64;

__device__ __forceinline__ u64 pk2(float lo, float hi) {
    u64 r; asm("mov.b64 %0,{%1,%2};" : "=l"(r) : "f"(lo), "f"(hi)); return r;
}
__device__ __forceinline__ void upk2(u64 v, float& lo, float& hi) {
    asm("mov.b64 {%0,%1},%2;" : "=f"(lo), "=f"(hi) : "l"(v));
}
__device__ __forceinline__ u64 ffma2(u64 a, u64 b, u64 c) {
    u64 d; asm("fma.rn.f32x2 %0,%1,%2,%3;" : "=l"(d) : "l"(a), "l"(b), "l"(c)); return d;
}
__device__ __forceinline__ u64 fadd2(u64 a, u64 b) {
    u64 d; asm("add.rn.f32x2 %0,%1,%2;" : "=l"(d) : "l"(a), "l"(b)); return d;
}
__device__ __forceinline__ u64 fmul2(u64 a, u64 b) {
    u64 d; asm("mul.rn.f32x2 %0,%1,%2;" : "=l"(d) : "l"(a), "l"(b)); return d;
}
__device__ __forceinline__ float ex2(float x) {
    float r; asm("ex2.approx.f32 %0,%1;" : "=f"(r) : "f"(x)); return r;
}

// One tap row (padded row = lr0 + 2*IROW) for the subset of the 2 pixels given
// by literal flags D0/D1 (dead chains removed at compile time).
#define TAP_ROW(IROW, D0, D1, B0, B1)                                          \
do {                                                                           \
    const int rowoff_ = (lr0 + 2 * (IROW)) * LW + tx;                          \
    _Pragma("unroll")                                                          \
    for (int j = 0; j < KS; j++) {                                             \
        const int p_ = rowoff_ + 2 * j;                                        \
        const float t_ = s2t[p_] + sxj[j];                                     \
        const ulonglong2 va = Tq[0 * PLANE + p_];                              \
        const ulonglong2 vb = Tq[1 * PLANE + p_];                              \
        const ulonglong2 vc = Tq[2 * PLANE + p_];                              \
        const ulonglong2 vd = Tq[3 * PLANE + p_];                              \
        float x0_, x1_, x2_, x3d_;                                             \
        upk2(va.x, x0_, x1_);                                                  \
        upk2(va.y, x2_, x3d_);                                                 \
        if (D0) {                                                              \
            u64 A0 = fmul2(y0p[0], va.x);                                      \
            u64 A1 = fmul2(y0p[1], va.y);                                      \
            A0 = ffma2(y0p[2], vb.x, A0);  A1 = ffma2(y0p[3], vb.y, A1);       \
            A0 = ffma2(y0p[4], vc.x, A0);  A1 = ffma2(y0p[5], vc.y, A1);       \
            A0 = ffma2(y0p[6], vd.x, A0);  A1 = ffma2(y0p[7], vd.y, A1);       \
            u64 SA = fadd2(A0, A1);                                            \
            float sl_, sh_;  upk2(SA, sl_, sh_);                               \
            const float w0_ = ex2((sl_ + sh_) + (t_ + (B0)));                  \
            n00 = fmaf(w0_, x0_, n00);                                         \
            n01 = fmaf(w0_, x1_, n01);                                         \
            n02 = fmaf(w0_, x2_, n02);                                         \
            d0 += w0_;                                                         \
        }                                                                      \
        if (D1) {                                                              \
            u64 B0c = fmul2(y1p[0], va.x);                                     \
            u64 B1c = fmul2(y1p[1], va.y);                                     \
            B0c = ffma2(y1p[2], vb.x, B0c);  B1c = ffma2(y1p[3], vb.y, B1c);   \
            B0c = ffma2(y1p[4], vc.x, B0c);  B1c = ffma2(y1p[5], vc.y, B1c);   \
            B0c = ffma2(y1p[6], vd.x, B0c);  B1c = ffma2(y1p[7], vd.y, B1c);   \
            u64 SB = fadd2(B0c, B1c);                                          \
            float sl_, sh_;  upk2(SB, sl_, sh_);                               \
            const float w1_ = ex2((sl_ + sh_) + (t_ + (B1)));                  \
            n10 = fmaf(w1_, x0_, n10);                                         \
            n11 = fmaf(w1_, x1_, n11);                                         \
            n12 = fmaf(w1_, x2_, n12);                                         \
            d1 += w1_;                                                         \
        }                                                                      \
    }                                                                          \
} while (0)

__global__ __launch_bounds__(NTHREADS, 2)
void bilateral_kernel(const float* __restrict__ in,
                      const float* __restrict__ prm,
                      float* __restrict__ out)
{
    extern __shared__ float smf[];
    // Quad-interleaved tile: ulonglong2 view [NQUAD][PLANE]; quad q holds ch 4q..4q+3
    ulonglong2* Tq  = (ulonglong2*)smf;
    float*      s2t = smf + CH * PLANE;     // [LH][LW], -1e30 marks OOB pixels

    const int tx  = threadIdx.x;         // 0..31
    const int ty  = threadIdx.y;         // 0..11
    const int tid = ty * TW + tx;
    const int bx0 = blockIdx.x * TW;
    const int by0 = blockIdx.y * TPH;
    const int b   = blockIdx.z;

    // Coefficients pre-scaled by log2(e) -> raw ex2
    float rcl[CH];
    #pragma unroll
    for (int c = 0; c < CH; c++) rcl[c] = __ldg(&prm[c]) * LOG2E;
    const float sxl = __ldg(&prm[CH]) * LOG2E;
    const float syl = __ldg(&prm[CH + 1]) * LOG2E;

    const float* inb = in + (size_t)b * CH * HH * WW;

    // ---- Phase 1: load haloed tile into quad-interleaved smem (zero-fill OOB) ----
    for (int idx = tid; idx < CH * PLANE; idx += NTHREADS) {
        int q    = idx / (4 * PLANE);
        int rem  = idx - q * (4 * PLANE);
        int p    = rem >> 2;
        int c    = 4 * q + (rem & 3);
        int lr = p / LW;
        int lc = p - lr * LW;
        int gy = by0 + lr - PAD;
        int gx = bx0 + lc - PAD;
        float v = 0.0f;
        if ((unsigned)gy < (unsigned)HH && (unsigned)gx < (unsigned)WW)
            v = __ldg(&inb[(size_t)c * HH * WW + (size_t)gy * WW + gx]);
        smf[idx] = v;
    }
    __syncthreads();

    // ---- Phase 2: s2'(q) = log2e * sum_c rc_c * x_c(q)^2 ; -1e30 where OOB ----
    for (int p = tid; p < PLANE; p += NTHREADS) {
        int lr = p / LW;
        int lc = p - lr * LW;
        int gy = by0 + lr - PAD;
        int gx = bx0 + lc - PAD;
        float s = -1e30f;
        if ((unsigned)gy < (unsigned)HH && (unsigned)gx < (unsigned)WW) {
            float a0 = 0.f, a1 = 0.f, a2 = 0.f, a3 = 0.f;
            #pragma unroll
            for (int q = 0; q < NQUAD; q++) {
                ulonglong2 v = Tq[q * PLANE + p];
                float x0, x1, x2, x3;
                upk2(v.x, x0, x1);
                upk2(v.y, x2, x3);
                a0 = fmaf(rcl[4*q + 0] * x0, x0, a0);
                a1 = fmaf(rcl[4*q + 1] * x1, x1, a1);
                a2 = fmaf(rcl[4*q + 2] * x2, x2, a2);
                a3 = fmaf(rcl[4*q + 3] * x3, x3, a3);
            }
            s = (a0 + a1) + (a2 + a3);
        }
        s2t[p] = s;
    }
    __syncthreads();

    // ---- Phase 3: two pixels per thread (rows lr0, lr0+2 share tap rows) ----
    // ty 0..11 -> lr0 = 4*(ty>>1)+(ty&1) in {0,1,4,5,8,9,12,13,16,17,20,21};
    // pairs {lr0, lr0+2} tile rows 0..23.
    const int lr0 = 4 * (ty >> 1) + (ty & 1);
    const int cp0 = (lr0 + PAD) * LW + (tx + PAD);
    const int cp1 = cp0 + 2 * LW;

    u64 rcn2[NPAIR];
    #pragma unroll
    for (int k = 0; k < NPAIR; k++)
        rcn2[k] = pk2(-2.0f * rcl[2*k], -2.0f * rcl[2*k + 1]);

    u64 y0p[NPAIR], y1p[NPAIR];
    #pragma unroll
    for (int q = 0; q < NQUAD; q++) {
        ulonglong2 v0 = Tq[q * PLANE + cp0];
        ulonglong2 v1 = Tq[q * PLANE + cp1];
        y0p[2*q]   = fmul2(rcn2[2*q],   v0.x);
        y0p[2*q+1] = fmul2(rcn2[2*q+1], v0.y);
        y1p[2*q]   = fmul2(rcn2[2*q],   v1.x);
        y1p[2*q+1] = fmul2(rcn2[2*q+1], v1.y);
    }
    const float s2p0 = s2t[cp0];
    const float s2p1 = s2t[cp1];

    float sxj[KS];
    #pragma unroll
    for (int j = 0; j < KS; j++) {
        float dxf = (float)((j - RAD) * DIL);
        sxj[j] = sxl * dxf * dxf;
    }

    float n00 = 0.f, n01 = 0.f, n02 = 0.f, d0 = 0.f;
    float n10 = 0.f, n11 = 0.f, n12 = 0.f, d1 = 0.f;

    // Row validity: px0 i in [0,6] (dy0=2i-6); px1 i in [1,7] (dy1=2i-8).
    // Peeled edge rows compute ONLY the valid pixel chain (no masked waste).
    TAP_ROW(0, 1, 0, fmaf(syl * 6.0f, 6.0f, s2p0), 0.0f);

    #pragma unroll 1
    for (int i = 1; i <= 6; i++) {
        const float dy0 = (float)(2 * i - 6);
        const float dy1 = (float)(2 * i - 8);
        const float base0 = fmaf(syl * dy0, dy0, s2p0);
        const float base1 = fmaf(syl * dy1, dy1, s2p1);
        TAP_ROW(i, 1, 1, base0, base1);
    }

    TAP_ROW(7, 0, 1, 0.0f, fmaf(syl * 6.0f, 6.0f, s2p1));

    const float inv0 = __fdividef(1.0f, d0);   // den >= 1 (center tap w=1)
    const float inv1 = __fdividef(1.0f, d1);
    const int gy0 = by0 + lr0;
    const int gy1 = gy0 + 2;
    const int gx  = bx0 + tx;
    const size_t CS = (size_t)HH * WW;
    const size_t ob = (size_t)b * DYN * CS + gx;
    if (gy0 < HH) {
        size_t o = ob + (size_t)gy0 * WW;
        out[o]          = n00 * inv0;
        out[o + CS]     = n01 * inv0;
        out[o + 2 * CS] = n02 * inv0;
    }
    if (gy1 < HH) {
        size_t o = ob + (size_t)gy1 * WW;
        out[o]          = n10 * inv1;
        out[o + CS]     = n11 * inv1;
        out[o + 2 * CS] = n12 * inv1;
    }
}

extern "C" void kernel_launch(void* const* d_in, const int* in_sizes, int n_in,
                              void* d_out, int out_size)
{
    const float* in  = (const float*)d_in[0];
    const float* prm = (const float*)d_in[1];
    float*       out = (float*)d_out;

    const int B = in_sizes[0] / (CH * HH * WW);   // = 4

    cudaFuncSetAttribute(bilateral_kernel,
                         cudaFuncAttributeMaxDynamicSharedMemorySize,
                         (int)SMEM_BYTES);

    dim3 block(TW, 12, 1);                             // 384 threads
    dim3 grid(WW / TW, (HH + TPH - 1) / TPH, B);       // 16 x 22 x 4
    bilateral_kernel<<<grid, block, SMEM_BYTES>>>(in, prm, out);
}